// round 7
// baseline (speedup 1.0000x reference)
#include <cuda_runtime.h>

typedef unsigned long long u64;

#define N_Q   9
#define C_CH  3
#define LEN   2048
#define LOUT  2046
#define BATCH 8
#define OCH   8
#define WPB   8
#define WU64  1056                       // u64 slots per warp region
#define DYNSZ (WPB * WU64 * 8)           // 67584 bytes dynamic smem

// ---------- packed f32x2 helpers ----------
__device__ __forceinline__ u64 pk2(float lo, float hi){
    u64 r; asm("mov.b64 %0, {%1, %2};" : "=l"(r) : "f"(lo), "f"(hi)); return r;
}
__device__ __forceinline__ float lo2(u64 v){
    float a; asm("{.reg .b32 h_; mov.b64 {%0, h_}, %1;}" : "=f"(a) : "l"(v)); return a;
}
__device__ __forceinline__ float hi2(u64 v){
    float a; asm("{.reg .b32 l_; mov.b64 {l_, %0}, %1;}" : "=f"(a) : "l"(v)); return a;
}
__device__ __forceinline__ u64 fma2(u64 a, u64 b, u64 c){
    u64 d; asm("fma.rn.f32x2 %0, %1, %2, %3;" : "=l"(d) : "l"(a), "l"(b), "l"(c)); return d;
}

// CNOT-ring permutation (replicates reference idx construction)
__device__ __forceinline__ int permref(int id){
#pragma unroll
    for (int c = 0; c < N_Q - 1; ++c){
        const int bit = (id >> (N_Q - 1 - c)) & 1;
        id ^= bit << (N_Q - 2 - c);
    }
    id ^= (id & 1) << (N_Q - 1);
    return id;
}

// float map for the perm scatter (same as validated R6)
__device__ __forceinline__ int smf(int j){
    return (j & 15) + 34 * ((j >> 4) & 15) + 560 * (j >> 8);
}

__global__ __launch_bounds__(256, 3)
void qconv_kernel(const float* __restrict__ x,
                  const float* __restrict__ theta,
                  float* __restrict__ out)
{
    extern __shared__ __align__(16) u64 dyn[];
    __shared__ u64   gttp[OCH / 2][8];   // (tan_o, tan_{o+1}) per qubit qi=0..7
    __shared__ float gtan[OCH][8];
    __shared__ float gc2[OCH * 8];
    __shared__ float gK[OCH];

    const int tid  = threadIdx.x;
    const int warp = tid >> 5;
    const int lane = tid & 31;
    const int t    = blockIdx.x;         // window position
    const int b    = warp;               // batch

    // ---- gate prep: phi = pi/4 - theta/2, tangent form ----
    if (tid < OCH * 8){
        const int o = tid >> 3, qi = tid & 7;          // qubit = qi+1
        const float th  = theta[o * N_Q + qi + 1];
        const float phi = 0.78539816339744830962f - 0.5f * th;
        float s, c; __sincosf(phi, &s, &c);
        gtan[o][qi] = __fdividef(s, c);
        gc2[tid]    = c * c;
    }
    __syncthreads();
    if (tid < 32){
        const int pr = tid >> 3, qi = tid & 7;
        gttp[pr][qi] = pk2(gtan[2 * pr][qi], gtan[2 * pr + 1][qi]);
    }
    if (tid < OCH){
        float k = 1.0f;
#pragma unroll
        for (int q = 0; q < 8; ++q) k *= gc2[tid * 8 + q];
        gK[tid] = k;
    }
    __syncthreads();

    u64*   S64 = dyn + warp * WU64;
    float* SF  = (float*)S64;
    const int llo = lane & 15;
    const int l4  = lane >> 4;

    // ---- WHT-domain per-qubit factors ----
    float av[N_Q], bv[N_Q];
#pragma unroll
    for (int i = 0; i < N_Q; ++i){
        const float xv = x[(b * C_CH + i / 3) * LEN + t + (i % 3)];
        float s, c; __sincosf(0.5f * xv, &s, &c);
        av[i] = c + s;
        bv[i] = c - s;
    }

    // ---- WHT(state) as product state, pre-scatter layout (scalar v[16]):
    //   jj[3:0]=llo -> qubits 8,7,6,5 ; jj[7:4]=r -> qubits 4,3,2,1 ; jj[8]=l4 -> qubit 0
    float lf = 0.044194173824159220275f;     // 1/sqrt(512)
    lf *= l4        ? bv[0] : av[0];
    lf *= (llo & 1) ? bv[8] : av[8];
    lf *= (llo & 2) ? bv[7] : av[7];
    lf *= (llo & 4) ? bv[6] : av[6];
    lf *= (llo & 8) ? bv[5] : av[5];

    float v[16];
    v[0] = lf;
#pragma unroll
    for (int bp = 0; bp < 4; ++bp){          // r bit bp -> qubit 4-bp
        const int q  = 4 - bp;
        const int sz = 1 << bp;
#pragma unroll
        for (int u = 0; u < 8; ++u) if (u < sz){
            v[u + sz] = v[u] * bv[q];
            v[u]      = v[u] * av[q];
        }
    }

    // ---- scatter through CNOT-ring perm; read base (layout A: j=lane<<4|r) ----
    const int pbase = permref((l4 << 8) | llo);
#pragma unroll
    for (int r = 0; r < 16; ++r)
        SF[smf(pbase ^ permref(r << 4))] = v[r];
    __syncwarp();

    float bse[16];
    {
        const float2* R = (const float2*)(SF + 34 * llo + 560 * l4);
#pragma unroll
        for (int p = 0; p < 8; ++p){
            const float2 w = R[p];
            bse[2 * p]     = w.x;
            bse[2 * p + 1] = w.y;
        }
    }

    // ---- channel pairs: pack = (channel o, channel o+1) ----
    // Layout A: j = lane<<4 | k ; j0..3 = qubits 8,7,6,5 (reg bits), j4..8 = lane.
    // Transpose swaps j7..4 <-> j3..0 (XOR-swizzled u64 map), j8 fixed.
    const float tsgn = (__popc(llo & 7) & 1) ? -1.0f : 1.0f;
    const int   s8   = llo >> 3;               // read-side bit3 relabel flag
    const u64   FLIPB = 0x8000000080000000ULL;

    u64* W0 = S64 + llo + 528 * l4;            // writes r<8  : W0[34r]
    u64* W1 = S64 + (llo ^ 8) + 528 * l4;      // writes r>=8 : W1[34r]
    const ulonglong2* RB = (const ulonglong2*)(S64 + 34 * llo + 528 * l4);

    for (int pr = 0; pr < 4; ++pr){
        const int o = 2 * pr;
        u64 Z[16];

        // qubit 8 (reg bit0) fused with pair init from scalar base
        {
            const float ta = gtan[o][7], tb_ = gtan[o + 1][7];
#pragma unroll
            for (int p = 0; p < 8; ++p){
                const float a0 = bse[2 * p], b0 = bse[2 * p + 1];
                Z[2 * p]     = pk2(fmaf( ta, b0, a0), fmaf( tb_, b0, a0));
                Z[2 * p + 1] = pk2(fmaf(-ta, a0, b0), fmaf(-tb_, a0, b0));
            }
        }
        // qubits 7,6,5 (reg bits 1,2,3)
#pragma unroll
        for (int k = 1; k < 4; ++k){
            const int m   = 1 << k;
            const u64 tb  = gttp[pr][7 - k];
            const u64 ntb = tb ^ FLIPB;
#pragma unroll
            for (int p = 0; p < 16; ++p) if (!(p & m)){
                const u64 A = Z[p], B = Z[p | m];
                Z[p]     = fma2(tb,  B, A);
                Z[p | m] = fma2(ntb, A, B);
            }
        }

        // u64 transpose (swap j7..4 <-> j3..0), conflict-free both directions
        __syncwarp();
#pragma unroll
        for (int r = 0; r < 8; ++r)  W0[34 * r] = Z[r];
#pragma unroll
        for (int r = 8; r < 16; ++r) W1[34 * r] = Z[r];
        __syncwarp();

        // read + fused qubit-4 rotation (new reg bit0)
        {
            const u64 tb4  = gttp[pr][3];
            const u64 ntb4 = tb4 ^ FLIPB;
#pragma unroll
            for (int kk = 0; kk < 8; ++kk){
                const ulonglong2 w = RB[kk];
                Z[2 * kk]     = fma2(tb4,  w.y, w.x);
                Z[2 * kk + 1] = fma2(ntb4, w.x, w.y);
            }
        }
        // qubits 3,2 (reg bits 1,2)
#pragma unroll
        for (int k = 1; k < 3; ++k){
            const int m   = 1 << k;
            const u64 tb  = gttp[pr][3 - k];
            const u64 ntb = tb ^ FLIPB;
#pragma unroll
            for (int p = 0; p < 16; ++p) if (!(p & m)){
                const u64 A = Z[p], B = Z[p | m];
                Z[p]     = fma2(tb,  B, A);
                Z[p | m] = fma2(ntb, A, B);
            }
        }
        // qubit 1 (reg bit 3) with s8 role swap (k = r' ^ 8*s8)
        {
            const u64 tb1  = gttp[pr][0];
            const u64 ntb1 = tb1 ^ FLIPB;
            const u64 ta   = s8 ? ntb1 : tb1;
            const u64 tb_  = s8 ? tb1  : ntb1;
#pragma unroll
            for (int p = 0; p < 8; ++p){
                const u64 A = Z[p], B = Z[p | 8];
                Z[p]     = fma2(ta,  B, A);
                Z[p | 8] = fma2(tb_, A, B);
            }
        }

        // signed squares: sign(j) = tsgn * (-1)^popc4(k)
        u64 accE = 0, accO = 0;
        accE = fma2(Z[0],  Z[0],  accE);  accO = fma2(Z[1],  Z[1],  accO);
        accO = fma2(Z[2],  Z[2],  accO);  accE = fma2(Z[3],  Z[3],  accE);
        accO = fma2(Z[4],  Z[4],  accO);  accE = fma2(Z[5],  Z[5],  accE);
        accE = fma2(Z[6],  Z[6],  accE);  accO = fma2(Z[7],  Z[7],  accO);
        accO = fma2(Z[8],  Z[8],  accO);  accE = fma2(Z[9],  Z[9],  accE);
        accE = fma2(Z[10], Z[10], accE);  accO = fma2(Z[11], Z[11], accO);
        accE = fma2(Z[12], Z[12], accE);  accO = fma2(Z[13], Z[13], accO);
        accO = fma2(Z[14], Z[14], accO);  accE = fma2(Z[15], Z[15], accE);

        // partials into map holes (u64 slots 34a+16..33, a=o): survive transposes
        SF[68 * o       + 32 + ((lane + 8 * o)       & 31)] =
            (lo2(accE) - lo2(accO)) * tsgn;
        SF[68 * (o + 1) + 32 + ((lane + 8 * (o + 1)) & 31)] =
            (hi2(accE) - hi2(accO)) * tsgn;
    }

    // ---- cooperative 8-channel reduction ----
    __syncwarp();
    {
        const int ch = lane >> 2;
        const int i  = lane & 3;
        const float4* P = (const float4*)(SF + 68 * ch + 32 + ((8 * (i + ch)) & 31));
        const float4 p0 = P[0], p1 = P[1];
        float tot = ((p0.x + p0.y) + (p0.z + p0.w)) +
                    ((p1.x + p1.y) + (p1.z + p1.w));
        tot += __shfl_xor_sync(0xffffffffu, tot, 1);
        tot += __shfl_xor_sync(0xffffffffu, tot, 2);
        if (i == 0)
            out[(b * OCH + ch) * LOUT + t] = tot * gK[ch];
    }
}

extern "C" void kernel_launch(void* const* d_in, const int* in_sizes, int n_in,
                              void* d_out, int out_size)
{
    const float* x_ptr  = nullptr;
    const float* th_ptr = nullptr;
    for (int i = 0; i < n_in; ++i){
        if (in_sizes[i] == BATCH * C_CH * LEN) x_ptr  = (const float*)d_in[i];
        else if (in_sizes[i] == OCH * N_Q)     th_ptr = (const float*)d_in[i];
    }
    if (!x_ptr)  x_ptr  = (const float*)d_in[0];
    if (!th_ptr) th_ptr = (const float*)d_in[n_in - 1];

    cudaFuncSetAttribute(qconv_kernel,
                         cudaFuncAttributeMaxDynamicSharedMemorySize, DYNSZ);
    qconv_kernel<<<LOUT, 256, DYNSZ>>>(x_ptr, th_ptr, (float*)d_out);
}

// round 9
// speedup vs baseline: 1.0009x; 1.0009x over previous
#include <cuda_runtime.h>

typedef unsigned long long u64;

#define N_Q   9
#define C_CH  3
#define LEN   2048
#define LOUT  2046
#define BATCH 8
#define OCH   8
#define WPB   8
#define WU64  832                        // 574 transpose/scatter + 256 bse spill (u64)
#define DYNSZ (WPB * WU64 * 8)           // 53248 bytes dynamic smem

// ---------- packed f32x2 helpers ----------
__device__ __forceinline__ u64 pk2(float lo, float hi){
    u64 r; asm("mov.b64 %0, {%1, %2};" : "=l"(r) : "f"(lo), "f"(hi)); return r;
}
__device__ __forceinline__ float lo2(u64 v){
    float a; asm("{.reg .b32 h_; mov.b64 {%0, h_}, %1;}" : "=f"(a) : "l"(v)); return a;
}
__device__ __forceinline__ float hi2(u64 v){
    float a; asm("{.reg .b32 l_; mov.b64 {l_, %0}, %1;}" : "=f"(a) : "l"(v)); return a;
}
__device__ __forceinline__ u64 fma2(u64 a, u64 b, u64 c){
    u64 d; asm("fma.rn.f32x2 %0, %1, %2, %3;" : "=l"(d) : "l"(a), "l"(b), "l"(c)); return d;
}

// CNOT-ring permutation (replicates reference idx construction)
__device__ __forceinline__ int permref(int id){
#pragma unroll
    for (int c = 0; c < N_Q - 1; ++c){
        const int bit = (id >> (N_Q - 1 - c)) & 1;
        id ^= bit << (N_Q - 2 - c);
    }
    id ^= (id & 1) << (N_Q - 1);
    return id;
}

// float map for the perm scatter (validated R6/R7); max float idx 1085 < 1148
__device__ __forceinline__ int smf(int j){
    return (j & 15) + 34 * ((j >> 4) & 15) + 560 * (j >> 8);
}

__global__ __launch_bounds__(256, 4)
void qconv_kernel(const float* __restrict__ x,
                  const float* __restrict__ theta,
                  float* __restrict__ out)
{
    extern __shared__ __align__(16) u64 dyn[];
    __shared__ u64   gttp[OCH / 2][8];   // (tan_o, tan_{o+1}) per qubit qi=0..7
    __shared__ float gtan[OCH][8];
    __shared__ float gc2[OCH * 8];
    __shared__ float gK[OCH];

    const int tid  = threadIdx.x;
    const int warp = tid >> 5;
    const int lane = tid & 31;
    const int t    = blockIdx.x;         // window position
    const int b    = warp;               // batch

    // ---- gate prep: phi = pi/4 - theta/2, tangent form ----
    if (tid < OCH * 8){
        const int o = tid >> 3, qi = tid & 7;          // qubit = qi+1
        const float th  = theta[o * N_Q + qi + 1];
        const float phi = 0.78539816339744830962f - 0.5f * th;
        float s, c; __sincosf(phi, &s, &c);
        gtan[o][qi] = __fdividef(s, c);
        gc2[tid]    = c * c;
    }
    __syncthreads();
    if (tid < 32){
        const int pr = tid >> 3, qi = tid & 7;
        gttp[pr][qi] = pk2(gtan[2 * pr][qi], gtan[2 * pr + 1][qi]);
    }
    if (tid < OCH){
        float k = 1.0f;
#pragma unroll
        for (int q = 0; q < 8; ++q) k *= gc2[tid * 8 + q];
        gK[tid] = k;
    }
    __syncthreads();

    u64*   S64   = dyn + warp * WU64;
    float* SF    = (float*)S64;
    u64*   SPILL = S64 + 576;            // bse spill region (576..831, disjoint)
    const int llo = lane & 15;
    const int l4  = lane >> 4;

    // ---- WHT-domain per-qubit factors ----
    float av[N_Q], bv[N_Q];
#pragma unroll
    for (int i = 0; i < N_Q; ++i){
        const float xv = x[(b * C_CH + i / 3) * LEN + t + (i % 3)];
        float s, c; __sincosf(0.5f * xv, &s, &c);
        av[i] = c + s;
        bv[i] = c - s;
    }

    // ---- WHT(state) as product state, pre-scatter layout (scalar v[16]) ----
    float lf = 0.044194173824159220275f;     // 1/sqrt(512)
    lf *= l4        ? bv[0] : av[0];
    lf *= (llo & 1) ? bv[8] : av[8];
    lf *= (llo & 2) ? bv[7] : av[7];
    lf *= (llo & 4) ? bv[6] : av[6];
    lf *= (llo & 8) ? bv[5] : av[5];

    float v[16];
    v[0] = lf;
#pragma unroll
    for (int bp = 0; bp < 4; ++bp){          // r bit bp -> qubit 4-bp
        const int q  = 4 - bp;
        const int sz = 1 << bp;
#pragma unroll
        for (int u = 0; u < 8; ++u) if (u < sz){
            v[u + sz] = v[u] * bv[q];
            v[u]      = v[u] * av[q];
        }
    }

    // ---- scatter through CNOT-ring perm ----
    const int pbase = permref((l4 << 8) | llo);
#pragma unroll
    for (int r = 0; r < 16; ++r)
        SF[smf(pbase ^ permref(r << 4))] = v[r];
    __syncwarp();

    // ---- read base (layout A) and spill as u64 pairs (own-thread identity) ----
    {
        const float2* R = (const float2*)(SF + 34 * llo + 560 * l4);
#pragma unroll
        for (int p = 0; p < 8; ++p){
            const float2 w = R[p];
            SPILL[lane + 32 * p] = pk2(w.x, w.y);
        }
    }

    // ---- channel pairs ----
    const float tsgn = (__popc(llo & 7) & 1) ? -1.0f : 1.0f;
    const int   s8   = llo >> 3;               // read-side bit3 relabel flag
    const u64   FLIPB = 0x8000000080000000ULL;

    // compact u64 transpose map: addr = (j7..4 ^ 8*j3) + 18*j3..0 + 288*j8
    u64* W0 = S64 + llo + 288 * l4;            // writes r<8  : W0[18r]
    u64* W1 = S64 + (llo ^ 8) + 288 * l4;      // writes r>=8 : W1[18r]
    const ulonglong2* RB = (const ulonglong2*)(S64 + 18 * llo + 288 * l4);

    u64 P[4];

    for (int pr = 0; pr < 4; ++pr){
        const int o = 2 * pr;
        u64 Z[16];

        // qubit 8 (reg bit0) fused with pair init from spilled base
        {
            const float ta = gtan[o][7], tb_ = gtan[o + 1][7];
#pragma unroll
            for (int p = 0; p < 8; ++p){
                const u64 w  = SPILL[lane + 32 * p];
                const float a0 = lo2(w), b0 = hi2(w);
                Z[2 * p]     = pk2(fmaf( ta, b0, a0), fmaf( tb_, b0, a0));
                Z[2 * p + 1] = pk2(fmaf(-ta, a0, b0), fmaf(-tb_, a0, b0));
            }
        }
        // qubits 7,6,5 (reg bits 1,2,3)
#pragma unroll
        for (int k = 1; k < 4; ++k){
            const int m   = 1 << k;
            const u64 tb  = gttp[pr][7 - k];
            const u64 ntb = tb ^ FLIPB;
#pragma unroll
            for (int p = 0; p < 16; ++p) if (!(p & m)){
                const u64 A = Z[p], B = Z[p | m];
                Z[p]     = fma2(tb,  B, A);
                Z[p | m] = fma2(ntb, A, B);
            }
        }

        // u64 transpose (swap j7..4 <-> j3..0), conflict-free both directions
        __syncwarp();
#pragma unroll
        for (int r = 0; r < 8; ++r)  W0[18 * r] = Z[r];
#pragma unroll
        for (int r = 8; r < 16; ++r) W1[18 * r] = Z[r];
        __syncwarp();

        // read + fused qubit-4 rotation (new reg bit0)
        {
            const u64 tb4  = gttp[pr][3];
            const u64 ntb4 = tb4 ^ FLIPB;
#pragma unroll
            for (int kk = 0; kk < 8; ++kk){
                const ulonglong2 w = RB[kk];
                Z[2 * kk]     = fma2(tb4,  w.y, w.x);
                Z[2 * kk + 1] = fma2(ntb4, w.x, w.y);
            }
        }
        // qubits 3,2 (reg bits 1,2)
#pragma unroll
        for (int k = 1; k < 3; ++k){
            const int m   = 1 << k;
            const u64 tb  = gttp[pr][3 - k];
            const u64 ntb = tb ^ FLIPB;
#pragma unroll
            for (int p = 0; p < 16; ++p) if (!(p & m)){
                const u64 A = Z[p], B = Z[p | m];
                Z[p]     = fma2(tb,  B, A);
                Z[p | m] = fma2(ntb, A, B);
            }
        }
        // qubit 1 (reg bit 3) with s8 role swap (k = r' ^ 8*s8)
        {
            const u64 tb1  = gttp[pr][0];
            const u64 ntb1 = tb1 ^ FLIPB;
            const u64 ta   = s8 ? ntb1 : tb1;
            const u64 tb_  = s8 ? tb1  : ntb1;
#pragma unroll
            for (int p = 0; p < 8; ++p){
                const u64 A = Z[p], B = Z[p | 8];
                Z[p]     = fma2(ta,  B, A);
                Z[p | 8] = fma2(tb_, A, B);
            }
        }

        // signed squares: sign(j) = tsgn * (-1)^popc4(k)
        u64 accE = 0, accO = 0;
        accE = fma2(Z[0],  Z[0],  accE);  accO = fma2(Z[1],  Z[1],  accO);
        accO = fma2(Z[2],  Z[2],  accO);  accE = fma2(Z[3],  Z[3],  accE);
        accO = fma2(Z[4],  Z[4],  accO);  accE = fma2(Z[5],  Z[5],  accE);
        accE = fma2(Z[6],  Z[6],  accE);  accO = fma2(Z[7],  Z[7],  accO);
        accO = fma2(Z[8],  Z[8],  accO);  accE = fma2(Z[9],  Z[9],  accE);
        accE = fma2(Z[10], Z[10], accE);  accO = fma2(Z[11], Z[11], accO);
        accE = fma2(Z[12], Z[12], accE);  accO = fma2(Z[13], Z[13], accO);
        accO = fma2(Z[14], Z[14], accO);  accE = fma2(Z[15], Z[15], accE);

        P[pr] = pk2((lo2(accE) - lo2(accO)) * tsgn,
                    (hi2(accE) - hi2(accO)) * tsgn);
    }

    // ---- partials into (now free) transpose region, R6-validated swizzle ----
    __syncwarp();
#pragma unroll
    for (int pr = 0; pr < 4; ++pr){
        const int o = 2 * pr;
        SF[o * 36       + ((lane + o)     & 31)] = lo2(P[pr]);
        SF[(o + 1) * 36 + ((lane + o + 1) & 31)] = hi2(P[pr]);
    }
    __syncwarp();

    // ---- cooperative 8-channel reduction: 8 LDS + 2 SHFL per thread ----
    {
        const int ch = lane >> 2;
        const int i  = lane & 3;
        float tot = 0.0f;
#pragma unroll
        for (int m = 0; m < 8; ++m)
            tot += SF[ch * 36 + ((8 * i + m + ch) & 31)];
        tot += __shfl_xor_sync(0xffffffffu, tot, 1);
        tot += __shfl_xor_sync(0xffffffffu, tot, 2);
        if (i == 0)
            out[(b * OCH + ch) * LOUT + t] = tot * gK[ch];
    }
}

extern "C" void kernel_launch(void* const* d_in, const int* in_sizes, int n_in,
                              void* d_out, int out_size)
{
    const float* x_ptr  = nullptr;
    const float* th_ptr = nullptr;
    for (int i = 0; i < n_in; ++i){
        if (in_sizes[i] == BATCH * C_CH * LEN) x_ptr  = (const float*)d_in[i];
        else if (in_sizes[i] == OCH * N_Q)     th_ptr = (const float*)d_in[i];
    }
    if (!x_ptr)  x_ptr  = (const float*)d_in[0];
    if (!th_ptr) th_ptr = (const float*)d_in[n_in - 1];

    cudaFuncSetAttribute(qconv_kernel,
                         cudaFuncAttributeMaxDynamicSharedMemorySize, DYNSZ);
    qconv_kernel<<<LOUT, 256, DYNSZ>>>(x_ptr, th_ptr, (float*)d_out);
}